// round 4
// baseline (speedup 1.0000x reference)
#include <cuda_runtime.h>
#include <cuda_bf16.h>

// ---------------- problem constants ----------------
#define BNB   16
#define SNS   64
#define CC    480
#define TT    8
#define FYH   28
#define FXW   28
#define OS8   8
#define NDF   256
#define KCENT 64
#define MROWS 1024              // BNB*SNS
#define KDIM  30720             // CC*OS8*OS8
#define HW    784               // FYH*FXW
#define NSPLIT 18
#define KCHUNK 1712             // 107 * 16 (last split gets 101 steps = 1616)

typedef unsigned long long u64;

// ---------------- device scratch (static, no allocations) ----------------
__device__ float g_featT[(size_t)BNB * HW * CC];           // [b][y][x][c]   24 MB
__device__ float g_A[(size_t)MROWS * KDIM];                // [row][p*480+c] 126 MB
__device__ float g_P[(size_t)NSPLIT * MROWS * NDF];        // split-K partials 18.9 MB

// ---------------- f32x2 packed-FMA helpers ----------------
__device__ __forceinline__ u64 splat2(float x) {
    u64 r; unsigned u = __float_as_uint(x);
    asm("mov.b64 %0, {%1, %2};" : "=l"(r) : "r"(u), "r"(u));
    return r;
}
__device__ __forceinline__ void fma2(u64& a, u64 x, u64 y) {
    asm("fma.rn.f32x2 %0, %1, %2, %0;" : "+l"(a) : "l"(x), "l"(y));
}
__device__ __forceinline__ float2 unpack2(u64 v) {
    unsigned lo, hi;
    asm("mov.b64 {%0, %1}, %2;" : "=r"(lo), "=r"(hi) : "l"(v));
    float2 f; f.x = __uint_as_float(lo); f.y = __uint_as_float(hi);
    return f;
}

// ---------------- K0: transpose feat [b][c][y][x] (T=last) -> [b][y][x][c] ----------------
__global__ void k_transpose(const float* __restrict__ zvis) {
    __shared__ float t[32][33];
    int b  = blockIdx.x;
    int c0 = blockIdx.y * 32;      // 15 tiles, exact (480)
    int h0 = blockIdx.z * 32;      // 25 tiles over 784 (guarded)
    int tx = threadIdx.x, ty = threadIdx.y;
    const float* src = zvis + (size_t)b * CC * TT * HW + (size_t)(TT - 1) * HW;
#pragma unroll
    for (int j = 0; j < 32; j += 8) {
        int c = c0 + ty + j, h = h0 + tx;
        t[ty + j][tx] = (h < HW) ? src[(size_t)c * (TT * HW) + h] : 0.f;
    }
    __syncthreads();
    float* dst = g_featT + (size_t)b * HW * CC;
#pragma unroll
    for (int j = 0; j < 32; j += 8) {
        int h = h0 + ty + j, c = c0 + tx;
        if (h < HW) dst[(size_t)h * CC + c] = t[tx][ty + j];
    }
}

// ---------------- K1: ROI-align pooling -> A[row][p*480+c] ----------------
__global__ void k_roi(const float* __restrict__ bboxs) {
    int row = blockIdx.x;          // 0..1023  (= b*64+s)
    int b   = row >> 6;
    __shared__ int   s_off[64][4];   // float4-index offsets into featT[b]
    __shared__ float s_w[64][4];
    __shared__ int   s_valid[64];
    int tid = threadIdx.x;
    if (tid < 64) {
        int p = tid;
        float bx1 = bboxs[row * 4 + 0], by1 = bboxs[row * 4 + 1];
        float bx2 = bboxs[row * 4 + 2], by2 = bboxs[row * 4 + 3];
        const float sX = 28.0f / 1920.0f, sY = 28.0f / 1080.0f;
        float x1 = bx1 * sX - 0.5f, y1 = by1 * sY - 0.5f;
        float x2 = bx2 * sX - 0.5f, y2 = by2 * sY - 0.5f;
        float bw = (x2 - x1) / 8.0f, bh = (y2 - y1) / 8.0f;
        int ix = p & 7, iy = p >> 3;
        float X = x1 + ((float)ix + 0.5f) * bw;
        float Y = y1 + ((float)iy + 0.5f) * bh;
        int valid = (Y > -1.0f) && (Y < 28.0f) && (X > -1.0f) && (X < 28.0f);
        float x = fminf(fmaxf(X, 0.f), 27.f);
        float y = fminf(fmaxf(Y, 0.f), 27.f);
        int x0 = (int)floorf(x), y0 = (int)floorf(y);
        int x1i = min(x0 + 1, 27), y1i = min(y0 + 1, 27);
        float lx = x - (float)x0, ly = y - (float)y0;
        s_off[p][0] = (y0 * 28 + x0) * (CC / 4);
        s_off[p][1] = (y0 * 28 + x1i) * (CC / 4);
        s_off[p][2] = (y1i * 28 + x0) * (CC / 4);
        s_off[p][3] = (y1i * 28 + x1i) * (CC / 4);
        s_w[p][0] = (1.f - ly) * (1.f - lx);
        s_w[p][1] = (1.f - ly) * lx;
        s_w[p][2] = ly * (1.f - lx);
        s_w[p][3] = ly * lx;
        s_valid[p] = valid;
    }
    __syncthreads();
    const float4* f = (const float4*)(g_featT + (size_t)b * HW * CC);
    float4* out = (float4*)(g_A + (size_t)row * KDIM);
    // 64 positions * 120 float4 per position
    for (int i = tid; i < 64 * 120; i += 256) {
        int p = i / 120, c4 = i - p * 120;
        float4 r = make_float4(0.f, 0.f, 0.f, 0.f);
        if (s_valid[p]) {
            float4 v00 = f[s_off[p][0] + c4];
            float4 v01 = f[s_off[p][1] + c4];
            float4 v10 = f[s_off[p][2] + c4];
            float4 v11 = f[s_off[p][3] + c4];
            float w0 = s_w[p][0], w1 = s_w[p][1], w2 = s_w[p][2], w3 = s_w[p][3];
            r.x = v00.x * w0 + v01.x * w1 + v10.x * w2 + v11.x * w3;
            r.y = v00.y * w0 + v01.y * w1 + v10.y * w2 + v11.y * w3;
            r.z = v00.z * w0 + v01.z * w1 + v10.z * w2 + v11.z * w3;
            r.w = v00.w * w0 + v01.w * w1 + v10.w * w2 + v11.w * w3;
        }
        out[p * 120 + c4] = r;
    }
}

// ---------------- K2: split-K GEMM  P[split] += A[128xK] * Wperm[Kx128] ----------------
#define BM 128
#define BN 128
#define BK 16

__global__ void __launch_bounds__(256, 2)
k_gemm(const float* __restrict__ W) {
    __shared__ float As[2][BK][BM + 4];
    __shared__ float Bs[2][BK][BN];

    const int n0 = blockIdx.x * BN;
    const int m0 = blockIdx.y * BM;
    const int split = blockIdx.z;
    const int kbeg = split * KCHUNK;
    const int ksteps = (split == NSPLIT - 1) ? 101 : 107;

    const int tid  = threadIdx.x;
    const int arow = tid >> 2;      // 0..63
    const int aq   = tid & 3;       // 0..3  (which 4-float chunk of the 16-wide k slab)
    const int brow = tid >> 5;      // 0..7
    const int bcol = tid & 31;      // 0..31

    const float* A0 = g_A + (size_t)(m0 + arow) * KDIM + aq * 4;
    const float* A1 = A0 + (size_t)64 * KDIM;

    float4 ra0, ra1, rb0, rb1;

    // initial stage load (kt = 0)
    {
        int kpos = kbeg;
        ra0 = *(const float4*)(A0 + kpos);
        ra1 = *(const float4*)(A1 + kpos);
        unsigned kg0 = (unsigned)(kpos + brow), kg1 = kg0 + 8u;
        unsigned p0 = kg0 / 480u, p1 = kg1 / 480u;
        rb0 = *(const float4*)(W + (size_t)((kg0 - p0 * 480u) * 64u + p0) * NDF + n0 + bcol * 4);
        rb1 = *(const float4*)(W + (size_t)((kg1 - p1 * 480u) * 64u + p1) * NDF + n0 + bcol * 4);
    }
    As[0][aq * 4 + 0][arow] = ra0.x; As[0][aq * 4 + 1][arow] = ra0.y;
    As[0][aq * 4 + 2][arow] = ra0.z; As[0][aq * 4 + 3][arow] = ra0.w;
    As[0][aq * 4 + 0][arow + 64] = ra1.x; As[0][aq * 4 + 1][arow + 64] = ra1.y;
    As[0][aq * 4 + 2][arow + 64] = ra1.z; As[0][aq * 4 + 3][arow + 64] = ra1.w;
    *(float4*)&Bs[0][brow][bcol * 4]     = rb0;
    *(float4*)&Bs[0][brow + 8][bcol * 4] = rb1;
    __syncthreads();

    u64 acc[8][4];
#pragma unroll
    for (int i = 0; i < 8; i++)
#pragma unroll
        for (int j = 0; j < 4; j++) acc[i][j] = 0ull;

    const int tm = tid >> 4;   // 0..15 -> rows tm*8..tm*8+7
    const int tn = tid & 15;   // 0..15 -> cols tn*8..tn*8+7

    int buf = 0;
    for (int kt = 0; kt < ksteps; ++kt) {
        if (kt + 1 < ksteps) {
            int kpos = kbeg + (kt + 1) * BK;
            ra0 = *(const float4*)(A0 + kpos);
            ra1 = *(const float4*)(A1 + kpos);
            unsigned kg0 = (unsigned)(kpos + brow), kg1 = kg0 + 8u;
            unsigned p0 = kg0 / 480u, p1 = kg1 / 480u;
            rb0 = *(const float4*)(W + (size_t)((kg0 - p0 * 480u) * 64u + p0) * NDF + n0 + bcol * 4);
            rb1 = *(const float4*)(W + (size_t)((kg1 - p1 * 480u) * 64u + p1) * NDF + n0 + bcol * 4);
        }
#pragma unroll
        for (int kk = 0; kk < BK; kk++) {
            float4 a0 = *(const float4*)&As[buf][kk][tm * 8];
            float4 a1 = *(const float4*)&As[buf][kk][tm * 8 + 4];
            ulonglong2 b0 = *(const ulonglong2*)&Bs[buf][kk][tn * 8];
            ulonglong2 b1 = *(const ulonglong2*)&Bs[buf][kk][tn * 8 + 4];
            u64 s;
            s = splat2(a0.x); fma2(acc[0][0], s, b0.x); fma2(acc[0][1], s, b0.y); fma2(acc[0][2], s, b1.x); fma2(acc[0][3], s, b1.y);
            s = splat2(a0.y); fma2(acc[1][0], s, b0.x); fma2(acc[1][1], s, b0.y); fma2(acc[1][2], s, b1.x); fma2(acc[1][3], s, b1.y);
            s = splat2(a0.z); fma2(acc[2][0], s, b0.x); fma2(acc[2][1], s, b0.y); fma2(acc[2][2], s, b1.x); fma2(acc[2][3], s, b1.y);
            s = splat2(a0.w); fma2(acc[3][0], s, b0.x); fma2(acc[3][1], s, b0.y); fma2(acc[3][2], s, b1.x); fma2(acc[3][3], s, b1.y);
            s = splat2(a1.x); fma2(acc[4][0], s, b0.x); fma2(acc[4][1], s, b0.y); fma2(acc[4][2], s, b1.x); fma2(acc[4][3], s, b1.y);
            s = splat2(a1.y); fma2(acc[5][0], s, b0.x); fma2(acc[5][1], s, b0.y); fma2(acc[5][2], s, b1.x); fma2(acc[5][3], s, b1.y);
            s = splat2(a1.z); fma2(acc[6][0], s, b0.x); fma2(acc[6][1], s, b0.y); fma2(acc[6][2], s, b1.x); fma2(acc[6][3], s, b1.y);
            s = splat2(a1.w); fma2(acc[7][0], s, b0.x); fma2(acc[7][1], s, b0.y); fma2(acc[7][2], s, b1.x); fma2(acc[7][3], s, b1.y);
        }
        if (kt + 1 < ksteps) {
            buf ^= 1;
            As[buf][aq * 4 + 0][arow] = ra0.x; As[buf][aq * 4 + 1][arow] = ra0.y;
            As[buf][aq * 4 + 2][arow] = ra0.z; As[buf][aq * 4 + 3][arow] = ra0.w;
            As[buf][aq * 4 + 0][arow + 64] = ra1.x; As[buf][aq * 4 + 1][arow + 64] = ra1.y;
            As[buf][aq * 4 + 2][arow + 64] = ra1.z; As[buf][aq * 4 + 3][arow + 64] = ra1.w;
            *(float4*)&Bs[buf][brow][bcol * 4]     = rb0;
            *(float4*)&Bs[buf][brow + 8][bcol * 4] = rb1;
            __syncthreads();
        }
    }

    float* dst = g_P + ((size_t)split * MROWS + (size_t)(m0 + tm * 8)) * NDF + n0 + tn * 8;
#pragma unroll
    for (int i = 0; i < 8; i++) {
        float2 c0 = unpack2(acc[i][0]);
        float2 c1 = unpack2(acc[i][1]);
        float2 c2 = unpack2(acc[i][2]);
        float2 c3 = unpack2(acc[i][3]);
        *(float4*)(dst + (size_t)i * NDF)     = make_float4(c0.x, c0.y, c1.x, c1.y);
        *(float4*)(dst + (size_t)i * NDF + 4) = make_float4(c2.x, c2.y, c3.x, c3.y);
    }
}

// ---------------- K3: reduce split-K + bias + spatial, distances, s, argmax ----------------
__global__ void k_final(const float* __restrict__ bboxs,
                        const float* __restrict__ b_vis,
                        const float* __restrict__ W_spc,
                        const float* __restrict__ b_spc,
                        const float* __restrict__ centroids,
                        float* __restrict__ out) {
    int row = blockIdx.x;     // 0..1023
    int tid = threadIdx.x;    // 256
    __shared__ float zs[NDF];
    __shared__ float sv[KCENT];
    __shared__ float ssum;

    // spatial norm term
    float bx1 = bboxs[row * 4 + 0], by1 = bboxs[row * 4 + 1];
    float bx2 = bboxs[row * 4 + 2], by2 = bboxs[row * 4 + 3];
    float cx = bx1 + (bx2 - bx1) * 0.5f;
    float cy = by1 + (by2 - by1) * 0.5f;
    float dx = cx - 960.0f, dy = cy - 540.0f;
    float nrm = sqrtf(dx * dx + dy * dy) / sqrtf(960.0f * 960.0f + 540.0f * 540.0f);

    float acc = 0.f;
#pragma unroll
    for (int s = 0; s < NSPLIT; s++)
        acc += g_P[((size_t)s * MROWS + row) * NDF + tid];
    float z = acc + b_vis[tid] + nrm * W_spc[tid] + b_spc[tid];
    out[(size_t)row * NDF + tid] = z;
    zs[tid] = z;
    __syncthreads();

    if (tid < KCENT) {
        const float* cen = centroids + (size_t)tid * NDF;
        float d2 = 0.f;
#pragma unroll 8
        for (int n = 0; n < NDF; n++) {
            float t = zs[n] - cen[n];
            d2 = fmaf(t, t, d2);
        }
        float d = sqrtf(d2);
        sv[tid] = 1.0f / (1.0f + d);    // (1 + d/alpha)^(-(alpha+1)/2), alpha=1
    }
    __syncthreads();
    if (tid < 32) {
        float v = sv[tid] + sv[tid + 32];
#pragma unroll
        for (int o = 16; o > 0; o >>= 1) v += __shfl_down_sync(0xffffffffu, v, o);
        if (tid == 0) ssum = v;
    }
    __syncthreads();
    if (tid < KCENT) {
        float s = sv[tid] / ssum;
        out[(size_t)MROWS * NDF + (size_t)row * KCENT + tid] = s;
        sv[tid] = s;
    }
    __syncthreads();
    if (tid == 0) {
        float best = sv[0]; int bi = 0;
#pragma unroll
        for (int k = 1; k < KCENT; k++)
            if (sv[k] > best) { best = sv[k]; bi = k; }
        out[(size_t)MROWS * NDF + (size_t)MROWS * KCENT + row] = (float)bi;
    }
}

// ---------------- launch ----------------
extern "C" void kernel_launch(void* const* d_in, const int* in_sizes, int n_in,
                              void* d_out, int out_size) {
    const float* z_vis = (const float*)d_in[0];
    const float* bboxs = (const float*)d_in[1];
    const float* W_vis = (const float*)d_in[2];
    const float* b_vis = (const float*)d_in[3];
    const float* W_spc = (const float*)d_in[4];
    const float* b_spc = (const float*)d_in[5];
    const float* cent  = (const float*)d_in[6];
    float* out = (float*)d_out;
    (void)in_sizes; (void)n_in; (void)out_size;

    k_transpose<<<dim3(16, 15, 25), dim3(32, 8)>>>(z_vis);
    k_roi<<<MROWS, 256>>>(bboxs);
    k_gemm<<<dim3(2, 8, NSPLIT), 256>>>(W_vis);
    k_final<<<MROWS, 256>>>(bboxs, b_vis, W_spc, b_spc, cent, out);
}

// round 5
// speedup vs baseline: 1.1449x; 1.1449x over previous
#include <cuda_runtime.h>
#include <cuda_bf16.h>

// ---------------- problem constants ----------------
#define BNB   16
#define SNS   64
#define CC    480
#define TT    8
#define FYH   28
#define FXW   28
#define OS8   8
#define NDF   256
#define KCENT 64
#define MROWS 1024              // BNB*SNS
#define KDIM  30720             // CC*OS8*OS8
#define HW    784               // FYH*FXW
#define NSPLIT 18
// split balance: 12 splits of 107 steps + 6 splits of 106 steps = 1920 steps total

typedef unsigned long long u64;

// ---------------- device scratch (static, no allocations) ----------------
__device__ float g_featT[(size_t)BNB * HW * CC];           // [b][y][x][c]   24 MB
__device__ float g_A[(size_t)MROWS * KDIM];                // [row][p*480+c] 126 MB
__device__ float g_P[(size_t)NSPLIT * MROWS * NDF];        // split-K partials 18.9 MB

// ---------------- f32x2 packed-FMA helpers ----------------
__device__ __forceinline__ u64 splat2(float x) {
    u64 r; unsigned u = __float_as_uint(x);
    asm("mov.b64 %0, {%1, %2};" : "=l"(r) : "r"(u), "r"(u));
    return r;
}
__device__ __forceinline__ void fma2(u64& a, u64 x, u64 y) {
    asm("fma.rn.f32x2 %0, %1, %2, %0;" : "+l"(a) : "l"(x), "l"(y));
}
__device__ __forceinline__ float2 unpack2(u64 v) {
    unsigned lo, hi;
    asm("mov.b64 {%0, %1}, %2;" : "=r"(lo), "=r"(hi) : "l"(v));
    float2 f; f.x = __uint_as_float(lo); f.y = __uint_as_float(hi);
    return f;
}

// ---------------- K0: transpose feat [b][c][y][x] (T=last) -> [b][y][x][c] ----------------
__global__ void k_transpose(const float* __restrict__ zvis) {
    __shared__ float t[32][33];
    int b  = blockIdx.x;
    int c0 = blockIdx.y * 32;      // 15 tiles, exact (480)
    int h0 = blockIdx.z * 32;      // 25 tiles over 784 (guarded)
    int tx = threadIdx.x, ty = threadIdx.y;
    const float* src = zvis + (size_t)b * CC * TT * HW + (size_t)(TT - 1) * HW;
#pragma unroll
    for (int j = 0; j < 32; j += 8) {
        int c = c0 + ty + j, h = h0 + tx;
        t[ty + j][tx] = (h < HW) ? src[(size_t)c * (TT * HW) + h] : 0.f;
    }
    __syncthreads();
    float* dst = g_featT + (size_t)b * HW * CC;
#pragma unroll
    for (int j = 0; j < 32; j += 8) {
        int h = h0 + ty + j, c = c0 + tx;
        if (h < HW) dst[(size_t)h * CC + c] = t[tx][ty + j];
    }
}

// ---------------- K1: ROI-align pooling -> A[row][p*480+c] ----------------
__global__ void k_roi(const float* __restrict__ bboxs) {
    int row = blockIdx.x;          // 0..1023  (= b*64+s)
    int b   = row >> 6;
    __shared__ int   s_off[64][4];   // float4-index offsets into featT[b]
    __shared__ float s_w[64][4];
    __shared__ int   s_valid[64];
    int tid = threadIdx.x;
    if (tid < 64) {
        int p = tid;
        float bx1 = bboxs[row * 4 + 0], by1 = bboxs[row * 4 + 1];
        float bx2 = bboxs[row * 4 + 2], by2 = bboxs[row * 4 + 3];
        const float sX = 28.0f / 1920.0f, sY = 28.0f / 1080.0f;
        float x1 = bx1 * sX - 0.5f, y1 = by1 * sY - 0.5f;
        float x2 = bx2 * sX - 0.5f, y2 = by2 * sY - 0.5f;
        float bw = (x2 - x1) / 8.0f, bh = (y2 - y1) / 8.0f;
        int ix = p & 7, iy = p >> 3;
        float X = x1 + ((float)ix + 0.5f) * bw;
        float Y = y1 + ((float)iy + 0.5f) * bh;
        int valid = (Y > -1.0f) && (Y < 28.0f) && (X > -1.0f) && (X < 28.0f);
        float x = fminf(fmaxf(X, 0.f), 27.f);
        float y = fminf(fmaxf(Y, 0.f), 27.f);
        int x0 = (int)floorf(x), y0 = (int)floorf(y);
        int x1i = min(x0 + 1, 27), y1i = min(y0 + 1, 27);
        float lx = x - (float)x0, ly = y - (float)y0;
        s_off[p][0] = (y0 * 28 + x0) * (CC / 4);
        s_off[p][1] = (y0 * 28 + x1i) * (CC / 4);
        s_off[p][2] = (y1i * 28 + x0) * (CC / 4);
        s_off[p][3] = (y1i * 28 + x1i) * (CC / 4);
        s_w[p][0] = (1.f - ly) * (1.f - lx);
        s_w[p][1] = (1.f - ly) * lx;
        s_w[p][2] = ly * (1.f - lx);
        s_w[p][3] = ly * lx;
        s_valid[p] = valid;
    }
    __syncthreads();
    const float4* f = (const float4*)(g_featT + (size_t)b * HW * CC);
    float4* out = (float4*)(g_A + (size_t)row * KDIM);
    // 64 positions * 120 float4 per position
    for (int i = tid; i < 64 * 120; i += 256) {
        int p = i / 120, c4 = i - p * 120;
        float4 r = make_float4(0.f, 0.f, 0.f, 0.f);
        if (s_valid[p]) {
            float4 v00 = f[s_off[p][0] + c4];
            float4 v01 = f[s_off[p][1] + c4];
            float4 v10 = f[s_off[p][2] + c4];
            float4 v11 = f[s_off[p][3] + c4];
            float w0 = s_w[p][0], w1 = s_w[p][1], w2 = s_w[p][2], w3 = s_w[p][3];
            r.x = v00.x * w0 + v01.x * w1 + v10.x * w2 + v11.x * w3;
            r.y = v00.y * w0 + v01.y * w1 + v10.y * w2 + v11.y * w3;
            r.z = v00.z * w0 + v01.z * w1 + v10.z * w2 + v11.z * w3;
            r.w = v00.w * w0 + v01.w * w1 + v10.w * w2 + v11.w * w3;
        }
        out[p * 120 + c4] = r;
    }
}

// ---------------- K2: split-K GEMM  P[split] = A[128xKc] * Wperm[Kcx128] ----------------
#define BM 128
#define BN 128
#define BK 16

__global__ void __launch_bounds__(256, 2)
k_gemm(const float* __restrict__ W) {
    __shared__ float As[2][BK][BM + 4];
    __shared__ float Bs[2][BK][BN];

    const int n0 = blockIdx.x * BN;
    const int m0 = blockIdx.y * BM;
    const int split = blockIdx.z;
    // balanced split-K: 12 splits of 107 steps, 6 splits of 106 steps (total 1920)
    const int ksteps = (split < 12) ? 107 : 106;
    const int kbeg = ((split < 12) ? (split * 107) : (12 * 107 + (split - 12) * 106)) * BK;

    const int tid  = threadIdx.x;
    const int arow = tid >> 2;      // 0..63
    const int aq   = tid & 3;       // 0..3  (which 4-float chunk of the 16-wide k slab)
    const int brow = tid >> 5;      // 0..7
    const int bcol = tid & 31;      // 0..31

    const float* A0 = g_A + (size_t)(m0 + arow) * KDIM + aq * 4;
    const float* A1 = A0 + (size_t)64 * KDIM;

    float4 ra0, ra1, rb0, rb1;

    // initial stage load (kt = 0)
    {
        int kpos = kbeg;
        ra0 = *(const float4*)(A0 + kpos);
        ra1 = *(const float4*)(A1 + kpos);
        unsigned kg0 = (unsigned)(kpos + brow), kg1 = kg0 + 8u;
        unsigned p0 = kg0 / 480u, p1 = kg1 / 480u;
        rb0 = *(const float4*)(W + (size_t)((kg0 - p0 * 480u) * 64u + p0) * NDF + n0 + bcol * 4);
        rb1 = *(const float4*)(W + (size_t)((kg1 - p1 * 480u) * 64u + p1) * NDF + n0 + bcol * 4);
    }
    As[0][aq * 4 + 0][arow] = ra0.x; As[0][aq * 4 + 1][arow] = ra0.y;
    As[0][aq * 4 + 2][arow] = ra0.z; As[0][aq * 4 + 3][arow] = ra0.w;
    As[0][aq * 4 + 0][arow + 64] = ra1.x; As[0][aq * 4 + 1][arow + 64] = ra1.y;
    As[0][aq * 4 + 2][arow + 64] = ra1.z; As[0][aq * 4 + 3][arow + 64] = ra1.w;
    *(float4*)&Bs[0][brow][bcol * 4]     = rb0;
    *(float4*)&Bs[0][brow + 8][bcol * 4] = rb1;
    __syncthreads();

    u64 acc[8][4];
#pragma unroll
    for (int i = 0; i < 8; i++)
#pragma unroll
        for (int j = 0; j < 4; j++) acc[i][j] = 0ull;

    const int tm = tid >> 4;   // 0..15 -> rows tm*8..tm*8+7
    const int tn = tid & 15;   // 0..15 -> cols tn*8..tn*8+7

    int buf = 0;
    for (int kt = 0; kt < ksteps; ++kt) {
        if (kt + 1 < ksteps) {
            int kpos = kbeg + (kt + 1) * BK;
            ra0 = *(const float4*)(A0 + kpos);
            ra1 = *(const float4*)(A1 + kpos);
            unsigned kg0 = (unsigned)(kpos + brow), kg1 = kg0 + 8u;
            unsigned p0 = kg0 / 480u, p1 = kg1 / 480u;
            rb0 = *(const float4*)(W + (size_t)((kg0 - p0 * 480u) * 64u + p0) * NDF + n0 + bcol * 4);
            rb1 = *(const float4*)(W + (size_t)((kg1 - p1 * 480u) * 64u + p1) * NDF + n0 + bcol * 4);
        }
#pragma unroll
        for (int kk = 0; kk < BK; kk++) {
            float4 a0 = *(const float4*)&As[buf][kk][tm * 8];
            float4 a1 = *(const float4*)&As[buf][kk][tm * 8 + 4];
            ulonglong2 b0 = *(const ulonglong2*)&Bs[buf][kk][tn * 8];
            ulonglong2 b1 = *(const ulonglong2*)&Bs[buf][kk][tn * 8 + 4];
            u64 s;
            s = splat2(a0.x); fma2(acc[0][0], s, b0.x); fma2(acc[0][1], s, b0.y); fma2(acc[0][2], s, b1.x); fma2(acc[0][3], s, b1.y);
            s = splat2(a0.y); fma2(acc[1][0], s, b0.x); fma2(acc[1][1], s, b0.y); fma2(acc[1][2], s, b1.x); fma2(acc[1][3], s, b1.y);
            s = splat2(a0.z); fma2(acc[2][0], s, b0.x); fma2(acc[2][1], s, b0.y); fma2(acc[2][2], s, b1.x); fma2(acc[2][3], s, b1.y);
            s = splat2(a0.w); fma2(acc[3][0], s, b0.x); fma2(acc[3][1], s, b0.y); fma2(acc[3][2], s, b1.x); fma2(acc[3][3], s, b1.y);
            s = splat2(a1.x); fma2(acc[4][0], s, b0.x); fma2(acc[4][1], s, b0.y); fma2(acc[4][2], s, b1.x); fma2(acc[4][3], s, b1.y);
            s = splat2(a1.y); fma2(acc[5][0], s, b0.x); fma2(acc[5][1], s, b0.y); fma2(acc[5][2], s, b1.x); fma2(acc[5][3], s, b1.y);
            s = splat2(a1.z); fma2(acc[6][0], s, b0.x); fma2(acc[6][1], s, b0.y); fma2(acc[6][2], s, b1.x); fma2(acc[6][3], s, b1.y);
            s = splat2(a1.w); fma2(acc[7][0], s, b0.x); fma2(acc[7][1], s, b0.y); fma2(acc[7][2], s, b1.x); fma2(acc[7][3], s, b1.y);
        }
        if (kt + 1 < ksteps) {
            buf ^= 1;
            As[buf][aq * 4 + 0][arow] = ra0.x; As[buf][aq * 4 + 1][arow] = ra0.y;
            As[buf][aq * 4 + 2][arow] = ra0.z; As[buf][aq * 4 + 3][arow] = ra0.w;
            As[buf][aq * 4 + 0][arow + 64] = ra1.x; As[buf][aq * 4 + 1][arow + 64] = ra1.y;
            As[buf][aq * 4 + 2][arow + 64] = ra1.z; As[buf][aq * 4 + 3][arow + 64] = ra1.w;
            *(float4*)&Bs[buf][brow][bcol * 4]     = rb0;
            *(float4*)&Bs[buf][brow + 8][bcol * 4] = rb1;
            __syncthreads();
        }
    }

    float* dst = g_P + ((size_t)split * MROWS + (size_t)(m0 + tm * 8)) * NDF + n0 + tn * 8;
#pragma unroll
    for (int i = 0; i < 8; i++) {
        float2 c0 = unpack2(acc[i][0]);
        float2 c1 = unpack2(acc[i][1]);
        float2 c2 = unpack2(acc[i][2]);
        float2 c3 = unpack2(acc[i][3]);
        *(float4*)(dst + (size_t)i * NDF)     = make_float4(c0.x, c0.y, c1.x, c1.y);
        *(float4*)(dst + (size_t)i * NDF + 4) = make_float4(c2.x, c2.y, c3.x, c3.y);
    }
}

// ---------------- K3: reduce split-K + bias + spatial, distances, s, argmax ----------------
// Rewritten: warp-per-8-centroids with COALESCED centroid reads (lanes scan n),
// shfl reductions, warp-parallel argmax. Old version had 64 threads each reading
// a different centroid row at the same n -> 64 L1 wavefronts per LDG (L1 80% busy).
__global__ void k_final(const float* __restrict__ bboxs,
                        const float* __restrict__ b_vis,
                        const float* __restrict__ W_spc,
                        const float* __restrict__ b_spc,
                        const float* __restrict__ centroids,
                        float* __restrict__ out) {
    int row  = blockIdx.x;     // 0..1023
    int tid  = threadIdx.x;    // 256
    int lane = tid & 31;
    int w    = tid >> 5;       // 0..7
    __shared__ float zs[NDF];
    __shared__ float sv[KCENT];
    __shared__ float s_sum;
    __shared__ int   s_arg;

    // spatial norm term (same op order as the passing version)
    float bx1 = bboxs[row * 4 + 0], by1 = bboxs[row * 4 + 1];
    float bx2 = bboxs[row * 4 + 2], by2 = bboxs[row * 4 + 3];
    float cx = bx1 + (bx2 - bx1) * 0.5f;
    float cy = by1 + (by2 - by1) * 0.5f;
    float dx = cx - 960.0f, dy = cy - 540.0f;
    float nrm = sqrtf(dx * dx + dy * dy) / sqrtf(960.0f * 960.0f + 540.0f * 540.0f);

    // split-K reduce: 18 independent coalesced LDGs (deep MLP)
    const float* P = g_P + (size_t)row * NDF + tid;
    float acc = 0.f;
#pragma unroll
    for (int s = 0; s < NSPLIT; s++)
        acc += P[(size_t)s * MROWS * NDF];
    float z = acc + b_vis[tid] + nrm * W_spc[tid] + b_spc[tid];
    out[(size_t)row * NDF + tid] = z;
    zs[tid] = z;
    __syncthreads();

    // distances: warp w handles centroids [8w, 8w+8); lanes scan n coalesced
#pragma unroll
    for (int kk = 0; kk < 8; kk++) {
        int k = w * 8 + kk;
        const float* cen = centroids + (size_t)k * NDF;
        float d2 = 0.f;
#pragma unroll
        for (int j = 0; j < 8; j++) {
            int n = j * 32 + lane;
            float t = zs[n] - cen[n];
            d2 = fmaf(t, t, d2);
        }
#pragma unroll
        for (int o = 16; o > 0; o >>= 1) d2 += __shfl_xor_sync(0xffffffffu, d2, o);
        if (lane == 0) sv[k] = 1.0f / (1.0f + sqrtf(d2));  // (1+d/a)^(-(a+1)/2), a=1
    }
    __syncthreads();

    // warp 0: sum + argmax (first-index tie rule, matching jnp.argmax)
    if (tid < 32) {
        float a = sv[tid], b = sv[tid + 32];
        float vsum = a + b;
        float m  = (a >= b) ? a : b;
        int   mi = (a >= b) ? tid : tid + 32;
#pragma unroll
        for (int o = 16; o > 0; o >>= 1) {
            vsum += __shfl_xor_sync(0xffffffffu, vsum, o);
            float om = __shfl_xor_sync(0xffffffffu, m, o);
            int   oi = __shfl_xor_sync(0xffffffffu, mi, o);
            if (om > m || (om == m && oi < mi)) { m = om; mi = oi; }
        }
        if (tid == 0) { s_sum = vsum; s_arg = mi; }
    }
    __syncthreads();

    if (tid < KCENT)
        out[(size_t)MROWS * NDF + (size_t)row * KCENT + tid] = sv[tid] / s_sum;
    if (tid == 0)
        out[(size_t)MROWS * NDF + (size_t)MROWS * KCENT + row] = (float)s_arg;
}

// ---------------- launch ----------------
extern "C" void kernel_launch(void* const* d_in, const int* in_sizes, int n_in,
                              void* d_out, int out_size) {
    const float* z_vis = (const float*)d_in[0];
    const float* bboxs = (const float*)d_in[1];
    const float* W_vis = (const float*)d_in[2];
    const float* b_vis = (const float*)d_in[3];
    const float* W_spc = (const float*)d_in[4];
    const float* b_spc = (const float*)d_in[5];
    const float* cent  = (const float*)d_in[6];
    float* out = (float*)d_out;
    (void)in_sizes; (void)n_in; (void)out_size;

    k_transpose<<<dim3(16, 15, 25), dim3(32, 8)>>>(z_vis);
    k_roi<<<MROWS, 256>>>(bboxs);
    k_gemm<<<dim3(2, 8, NSPLIT), 256>>>(W_vis);
    k_final<<<MROWS, 256>>>(bboxs, b_vis, W_spc, b_spc, cent, out);
}

// round 7
// speedup vs baseline: 2.1768x; 1.9014x over previous
#include <cuda_runtime.h>
#include <cuda_bf16.h>
#include <cstdint>

// ---------------- problem constants ----------------
#define BNB   16
#define SNS   64
#define CC    480
#define TT    8
#define FYH   28
#define FXW   28
#define OS8   8
#define NDF   256
#define KCENT 64
#define MROWS 1024              // BNB*SNS
#define KDIM  30720             // CC*OS8*OS8
#define HW    784               // FYH*FXW
#define NSPLIT 9                // split-K ways (6x107 + 3x106 slabs of k=32)

// ---------------- device scratch (static, no allocations) ----------------
__device__ float          g_featT[(size_t)BNB * HW * CC];     // [b][y][x][c] fp32
__device__ __nv_bfloat16  g_Ah[(size_t)MROWS * KDIM];         // A hi  [row][p*480+c]
__device__ __nv_bfloat16  g_Al[(size_t)MROWS * KDIM];         // A lo
__device__ __nv_bfloat16  g_Wh[(size_t)NDF * KDIM];           // Wt hi [n][p*480+c]
__device__ __nv_bfloat16  g_Wl[(size_t)NDF * KDIM];           // Wt lo
__device__ float          g_P[(size_t)NSPLIT * MROWS * NDF];  // split-K partials

// ---------------- helpers ----------------
#define SMEM_SWIZZLE_128B(byte_offset) \
    ((byte_offset) ^ (((byte_offset) >> 3) & 0x70))

__device__ __forceinline__ uint32_t smem_to_u32(const void* p) {
    uint32_t a;
    asm("{ .reg .u64 t; cvta.to.shared.u64 t, %1; cvt.u32.u64 %0, t; }" : "=r"(a) : "l"(p));
    return a;
}
__device__ __forceinline__ unsigned short bf16u(float x) {
    __nv_bfloat16 h = __float2bfloat16(x);
    return __bfloat16_as_ushort(h);
}
__device__ __forceinline__ float bf16f(unsigned short u) {
    return __bfloat162float(__ushort_as_bfloat16(u));
}

#define LDSM4(R0, R1, R2, R3, ADDR) \
    asm volatile("ldmatrix.sync.aligned.m8n8.x4.shared.b16 {%0,%1,%2,%3}, [%4];" \
        : "=r"(R0), "=r"(R1), "=r"(R2), "=r"(R3) : "r"(ADDR))

#define MMA16816(C, A, B0, B1) \
    asm volatile("mma.sync.aligned.m16n8k16.row.col.f32.bf16.bf16.f32 " \
        "{%0,%1,%2,%3}, {%4,%5,%6,%7}, {%8,%9}, {%0,%1,%2,%3};" \
        : "+f"((C)[0]), "+f"((C)[1]), "+f"((C)[2]), "+f"((C)[3]) \
        : "r"((A)[0]), "r"((A)[1]), "r"((A)[2]), "r"((A)[3]), "r"(B0), "r"(B1))

#define CPA16(DST, SRC) \
    asm volatile("cp.async.cg.shared.global [%0], [%1], 16;" :: "r"(DST), "l"(SRC))
#define CPA_COMMIT() asm volatile("cp.async.commit_group;" ::: "memory")
#define CPA_WAIT(N)  asm volatile("cp.async.wait_group %0;" :: "n"(N) : "memory")

// ---------------- K0: transpose feat [b][c][y][x] (T=last) -> [b][y][x][c] ----------------
__global__ void k_transpose(const float* __restrict__ zvis) {
    __shared__ float t[32][33];
    int b  = blockIdx.x;
    int c0 = blockIdx.y * 32;
    int h0 = blockIdx.z * 32;
    int tx = threadIdx.x, ty = threadIdx.y;
    const float* src = zvis + (size_t)b * CC * TT * HW + (size_t)(TT - 1) * HW;
#pragma unroll
    for (int j = 0; j < 32; j += 8) {
        int c = c0 + ty + j, h = h0 + tx;
        t[ty + j][tx] = (h < HW) ? src[(size_t)c * (TT * HW) + h] : 0.f;
    }
    __syncthreads();
    float* dst = g_featT + (size_t)b * HW * CC;
#pragma unroll
    for (int j = 0; j < 32; j += 8) {
        int h = h0 + ty + j, c = c0 + tx;
        if (h < HW) dst[(size_t)h * CC + c] = t[tx][ty + j];
    }
}

// ---------------- K0b: transpose+permute W[c*64+p][n] -> Wt hi/lo [n][p*480+c] ----------------
__global__ void k_wt(const float* __restrict__ W) {
    __shared__ float t[32][33];
    int kg0 = blockIdx.x * 32;     // 960 tiles over KDIM
    int n0  = blockIdx.y * 32;     // 8 tiles over NDF
    int tx = threadIdx.x, ty = threadIdx.y;   // 32 x 8
#pragma unroll
    for (int j = 0; j < 32; j += 8) {
        int kg = kg0 + ty + j;
        int c = kg % 480, p = kg / 480;
        t[ty + j][tx] = W[(size_t)(c * 64 + p) * NDF + n0 + tx];
    }
    __syncthreads();
#pragma unroll
    for (int j = 0; j < 32; j += 8) {
        int n = n0 + ty + j;
        float v = t[tx][ty + j];
        unsigned short h = bf16u(v);
        unsigned short l = bf16u(v - bf16f(h));
        g_Wh[(size_t)n * KDIM + kg0 + tx] = __ushort_as_bfloat16(h);
        g_Wl[(size_t)n * KDIM + kg0 + tx] = __ushort_as_bfloat16(l);
    }
}

// ---------------- K1: ROI-align pooling -> A hi/lo bf16 [row][p*480+c] ----------------
__global__ void k_roi(const float* __restrict__ bboxs) {
    int row = blockIdx.x;
    int b   = row >> 6;
    __shared__ int   s_off[64][4];
    __shared__ float s_w[64][4];
    __shared__ int   s_valid[64];
    int tid = threadIdx.x;
    if (tid < 64) {
        int p = tid;
        float bx1 = bboxs[row * 4 + 0], by1 = bboxs[row * 4 + 1];
        float bx2 = bboxs[row * 4 + 2], by2 = bboxs[row * 4 + 3];
        const float sX = 28.0f / 1920.0f, sY = 28.0f / 1080.0f;
        float x1 = bx1 * sX - 0.5f, y1 = by1 * sY - 0.5f;
        float x2 = bx2 * sX - 0.5f, y2 = by2 * sY - 0.5f;
        float bw = (x2 - x1) / 8.0f, bh = (y2 - y1) / 8.0f;
        int ix = p & 7, iy = p >> 3;
        float X = x1 + ((float)ix + 0.5f) * bw;
        float Y = y1 + ((float)iy + 0.5f) * bh;
        int valid = (Y > -1.0f) && (Y < 28.0f) && (X > -1.0f) && (X < 28.0f);
        float x = fminf(fmaxf(X, 0.f), 27.f);
        float y = fminf(fmaxf(Y, 0.f), 27.f);
        int x0 = (int)floorf(x), y0 = (int)floorf(y);
        int x1i = min(x0 + 1, 27), y1i = min(y0 + 1, 27);
        float lx = x - (float)x0, ly = y - (float)y0;
        s_off[p][0] = (y0 * 28 + x0) * (CC / 4);
        s_off[p][1] = (y0 * 28 + x1i) * (CC / 4);
        s_off[p][2] = (y1i * 28 + x0) * (CC / 4);
        s_off[p][3] = (y1i * 28 + x1i) * (CC / 4);
        s_w[p][0] = (1.f - ly) * (1.f - lx);
        s_w[p][1] = (1.f - ly) * lx;
        s_w[p][2] = ly * (1.f - lx);
        s_w[p][3] = ly * lx;
        s_valid[p] = valid;
    }
    __syncthreads();
    const float4* f = (const float4*)(g_featT + (size_t)b * HW * CC);
    uint2* outh = (uint2*)(g_Ah + (size_t)row * KDIM);
    uint2* outl = (uint2*)(g_Al + (size_t)row * KDIM);
    for (int i = tid; i < 64 * 120; i += 256) {
        int p = i / 120, c4 = i - p * 120;
        float4 r = make_float4(0.f, 0.f, 0.f, 0.f);
        if (s_valid[p]) {
            float4 v00 = f[s_off[p][0] + c4];
            float4 v01 = f[s_off[p][1] + c4];
            float4 v10 = f[s_off[p][2] + c4];
            float4 v11 = f[s_off[p][3] + c4];
            float w0 = s_w[p][0], w1 = s_w[p][1], w2 = s_w[p][2], w3 = s_w[p][3];
            r.x = v00.x * w0 + v01.x * w1 + v10.x * w2 + v11.x * w3;
            r.y = v00.y * w0 + v01.y * w1 + v10.y * w2 + v11.y * w3;
            r.z = v00.z * w0 + v01.z * w1 + v10.z * w2 + v11.z * w3;
            r.w = v00.w * w0 + v01.w * w1 + v10.w * w2 + v11.w * w3;
        }
        unsigned short h0 = bf16u(r.x), h1 = bf16u(r.y), h2 = bf16u(r.z), h3 = bf16u(r.w);
        unsigned short l0 = bf16u(r.x - bf16f(h0));
        unsigned short l1 = bf16u(r.y - bf16f(h1));
        unsigned short l2 = bf16u(r.z - bf16f(h2));
        unsigned short l3 = bf16u(r.w - bf16f(h3));
        outh[p * 120 + c4] = make_uint2((uint32_t)h0 | ((uint32_t)h1 << 16),
                                        (uint32_t)h2 | ((uint32_t)h3 << 16));
        outl[p * 120 + c4] = make_uint2((uint32_t)l0 | ((uint32_t)l1 << 16),
                                        (uint32_t)l2 | ((uint32_t)l3 << 16));
    }
}

// ---------------- K2: bf16x3 warp-MMA split-K GEMM ----------------
// CTA 128M x 128N, K slab = 32. smem stage = 4 tiles (Ahi,Alo,Bhi,Blo) of
// 128x32 bf16 = 8KB each, 2 stages = 64KB. Tiles swizzled with SW128 so both
// cp.async stores and ldmatrix octet reads are bank-conflict-free.
#define G3_TILE  8192
#define G3_STAGE 32768
#define G3_DYN   (65536 + 1024)

__global__ void __launch_bounds__(256, 1) k_gemm3() {
    extern __shared__ char smem[];
    uint32_t sbase = (smem_to_u32(smem) + 1023u) & ~1023u;

    const int tid  = threadIdx.x;
    const int lane = tid & 31;
    const int wid  = tid >> 5;          // 0..7
    const int wm   = wid & 3;           // M warp 0..3 (32 rows each)
    const int wn   = wid >> 2;          // N warp 0..1 (64 cols each)

    const int n0    = blockIdx.x * 128; // 2 N tiles
    const int m0    = blockIdx.y * 128; // 8 M tiles
    const int split = blockIdx.z;       // 9 splits
    const int nsl   = (split < 6) ? 107 : 106;
    const int kbeg  = ((split < 6) ? split * 107 : 642 + (split - 6) * 106) * 32;

    // ---- cp.async per-thread mapping: chunk id = tid (rows 0..63) and tid+256 (rows 64..127)
    const int cr = tid >> 2;            // row 0..63
    const int cc = tid & 3;             // 16B chunk in 64B row
    const uint32_t dst0 = SMEM_SWIZZLE_128B((uint32_t)(cr * 64 + cc * 16));
    const uint32_t dst1 = SMEM_SWIZZLE_128B((uint32_t)((cr + 64) * 64 + cc * 16));
    const __nv_bfloat16* pAh  = g_Ah + (size_t)(m0 + cr) * KDIM + cc * 8;
    const __nv_bfloat16* pAh2 = pAh + (size_t)64 * KDIM;
    const __nv_bfloat16* pAl  = g_Al + (size_t)(m0 + cr) * KDIM + cc * 8;
    const __nv_bfloat16* pAl2 = pAl + (size_t)64 * KDIM;
    const __nv_bfloat16* pBh  = g_Wh + (size_t)(n0 + cr) * KDIM + cc * 8;
    const __nv_bfloat16* pBh2 = pBh + (size_t)64 * KDIM;
    const __nv_bfloat16* pBl  = g_Wl + (size_t)(n0 + cr) * KDIM + cc * 8;
    const __nv_bfloat16* pBl2 = pBl + (size_t)64 * KDIM;

    // ---- ldmatrix per-lane swizzled offsets
    const int o = lane >> 3, li = lane & 7;
    uint32_t offA[2][2], offB[4][2];
#pragma unroll
    for (int mt = 0; mt < 2; mt++)
#pragma unroll
        for (int kb = 0; kb < 2; kb++) {
            int row  = wm * 32 + mt * 16 + (o & 1) * 8 + li;
            int colb = (o >> 1) * 16 + kb * 32;
            offA[mt][kb] = SMEM_SWIZZLE_128B((uint32_t)(row * 64 + colb));
        }
#pragma unroll
    for (int g4 = 0; g4 < 4; g4++)
#pragma unroll
        for (int kb = 0; kb < 2; kb++) {
            int row  = wn * 64 + g4 * 16 + (o >> 1) * 8 + li;
            int colb = (o & 1) * 16 + kb * 32;
            offB[g4][kb] = SMEM_SWIZZLE_128B((uint32_t)(row * 64 + colb));
        }

    float C[2][8][4];
#pragma unroll
    for (int mt = 0; mt < 2; mt++)
#pragma unroll
        for (int nt = 0; nt < 8; nt++)
#pragma unroll
            for (int q = 0; q < 4; q++) C[mt][nt][q] = 0.f;

    // ---- stage loader
    auto load_stage = [&](int s, int buf) {
        int kpos = kbeg + s * 32;
        uint32_t st = sbase + (uint32_t)buf * G3_STAGE;
        CPA16(st + dst0,            pAh  + kpos);
        CPA16(st + dst1,            pAh2 + kpos);
        CPA16(st +  8192u + dst0,   pAl  + kpos);
        CPA16(st +  8192u + dst1,   pAl2 + kpos);
        CPA16(st + 16384u + dst0,   pBh  + kpos);
        CPA16(st + 16384u + dst1,   pBh2 + kpos);
        CPA16(st + 24576u + dst0,   pBl  + kpos);
        CPA16(st + 24576u + dst1,   pBl2 + kpos);
        CPA_COMMIT();
    };

    load_stage(0, 0);

    for (int s = 0; s < nsl; s++) {
        int buf = s & 1;
        if (s + 1 < nsl) {
            load_stage(s + 1, buf ^ 1);
            CPA_WAIT(1);
        } else {
            CPA_WAIT(0);
        }
        __syncthreads();

        uint32_t base = sbase + (uint32_t)buf * G3_STAGE;
#pragma unroll
        for (int kb = 0; kb < 2; kb++) {
            uint32_t Ah[2][4], Al[2][4], Bh[8][2], Bl[8][2];
            LDSM4(Ah[0][0], Ah[0][1], Ah[0][2], Ah[0][3], base + offA[0][kb]);
            LDSM4(Ah[1][0], Ah[1][1], Ah[1][2], Ah[1][3], base + offA[1][kb]);
            LDSM4(Al[0][0], Al[0][1], Al[0][2], Al[0][3], base + 8192u + offA[0][kb]);
            LDSM4(Al[1][0], Al[1][1], Al[1][2], Al[1][3], base + 8192u + offA[1][kb]);
#pragma unroll
            for (int g4 = 0; g4 < 4; g4++)
                LDSM4(Bh[2 * g4][0], Bh[2 * g4][1], Bh[2 * g4 + 1][0], Bh[2 * g4 + 1][1],
                      base + 16384u + offB[g4][kb]);
#pragma unroll
            for (int g4 = 0; g4 < 4; g4++)
                LDSM4(Bl[2 * g4][0], Bl[2 * g4][1], Bl[2 * g4 + 1][0], Bl[2 * g4 + 1][1],
                      base + 24576u + offB[g4][kb]);
#pragma unroll
            for (int mt = 0; mt < 2; mt++)
#pragma unroll
                for (int nt = 0; nt < 8; nt++) {
                    MMA16816(C[mt][nt], Ah[mt], Bh[nt][0], Bh[nt][1]);
                    MMA16816(C[mt][nt], Ah[mt], Bl[nt][0], Bl[nt][1]);
                    MMA16816(C[mt][nt], Al[mt], Bh[nt][0], Bh[nt][1]);
                }
        }
        __syncthreads();
    }

    // ---- epilogue: C frags -> g_P (quad-contiguous 32B segments)
    float* dst = g_P + (size_t)split * MROWS * NDF;
    const int gq = lane >> 2, tq = lane & 3;
#pragma unroll
    for (int mt = 0; mt < 2; mt++)
#pragma unroll
        for (int nt = 0; nt < 8; nt++) {
            int rr = m0 + wm * 32 + mt * 16 + gq;
            int nn = n0 + wn * 64 + nt * 8 + tq * 2;
            *(float2*)(dst + (size_t)rr * NDF + nn)       = make_float2(C[mt][nt][0], C[mt][nt][1]);
            *(float2*)(dst + (size_t)(rr + 8) * NDF + nn) = make_float2(C[mt][nt][2], C[mt][nt][3]);
        }
}

// ---------------- K3: reduce split-K + bias + spatial, distances, s, argmax ----------------
__global__ void k_final(const float* __restrict__ bboxs,
                        const float* __restrict__ b_vis,
                        const float* __restrict__ W_spc,
                        const float* __restrict__ b_spc,
                        const float* __restrict__ centroids,
                        float* __restrict__ out) {
    int row  = blockIdx.x;
    int tid  = threadIdx.x;
    int lane = tid & 31;
    int w    = tid >> 5;
    __shared__ float zs[NDF];
    __shared__ float sv[KCENT];
    __shared__ float s_sum;
    __shared__ int   s_arg;

    float bx1 = bboxs[row * 4 + 0], by1 = bboxs[row * 4 + 1];
    float bx2 = bboxs[row * 4 + 2], by2 = bboxs[row * 4 + 3];
    float cx = bx1 + (bx2 - bx1) * 0.5f;
    float cy = by1 + (by2 - by1) * 0.5f;
    float dx = cx - 960.0f, dy = cy - 540.0f;
    float nrm = sqrtf(dx * dx + dy * dy) / sqrtf(960.0f * 960.0f + 540.0f * 540.0f);

    const float* P = g_P + (size_t)row * NDF + tid;
    float acc = 0.f;
#pragma unroll
    for (int s = 0; s < NSPLIT; s++)
        acc += P[(size_t)s * MROWS * NDF];
    float z = acc + b_vis[tid] + nrm * W_spc[tid] + b_spc[tid];
    out[(size_t)row * NDF + tid] = z;
    zs[tid] = z;
    __syncthreads();

#pragma unroll
    for (int kk = 0; kk < 8; kk++) {
        int k = w * 8 + kk;
        const float* cen = centroids + (size_t)k * NDF;
        float d2 = 0.f;
#pragma unroll
        for (int j = 0; j < 8; j++) {
            int n = j * 32 + lane;
            float t = zs[n] - cen[n];
            d2 = fmaf(t, t, d2);
        }
#pragma unroll
        for (int oo = 16; oo > 0; oo >>= 1) d2 += __shfl_xor_sync(0xffffffffu, d2, oo);
        if (lane == 0) sv[k] = 1.0f / (1.0f + sqrtf(d2));
    }
    __syncthreads();

    if (tid < 32) {
        float a = sv[tid], b = sv[tid + 32];
        float vsum = a + b;
        float m  = (a >= b) ? a : b;
        int   mi = (a >= b) ? tid : tid + 32;
#pragma unroll
        for (int oo = 16; oo > 0; oo >>= 1) {
            vsum += __shfl_xor_sync(0xffffffffu, vsum, oo);
            float om = __shfl_xor_sync(0xffffffffu, m, oo);
            int   oi = __shfl_xor_sync(0xffffffffu, mi, oo);
            if (om > m || (om == m && oi < mi)) { m = om; mi = oi; }
        }
        if (tid == 0) { s_sum = vsum; s_arg = mi; }
    }
    __syncthreads();

    if (tid < KCENT)
        out[(size_t)MROWS * NDF + (size_t)row * KCENT + tid] = sv[tid] / s_sum;
    if (tid == 0)
        out[(size_t)MROWS * NDF + (size_t)MROWS * KCENT + row] = (float)s_arg;
}

// ---------------- launch ----------------
extern "C" void kernel_launch(void* const* d_in, const int* in_sizes, int n_in,
                              void* d_out, int out_size) {
    const float* z_vis = (const float*)d_in[0];
    const float* bboxs = (const float*)d_in[1];
    const float* W_vis = (const float*)d_in[2];
    const float* b_vis = (const float*)d_in[3];
    const float* W_spc = (const float*)d_in[4];
    const float* b_spc = (const float*)d_in[5];
    const float* cent  = (const float*)d_in[6];
    float* out = (float*)d_out;
    (void)in_sizes; (void)n_in; (void)out_size;

    cudaFuncSetAttribute(k_gemm3, cudaFuncAttributeMaxDynamicSharedMemorySize, G3_DYN);

    k_transpose<<<dim3(16, 15, 25), dim3(32, 8)>>>(z_vis);
    k_wt<<<dim3(KDIM / 32, NDF / 32), dim3(32, 8)>>>(W_vis);
    k_roi<<<MROWS, 256>>>(bboxs);
    k_gemm3<<<dim3(2, 8, NSPLIT), 256, G3_DYN>>>();
    k_final<<<MROWS, 256>>>(bboxs, b_vis, W_spc, b_spc, cent, out);
}

// round 8
// speedup vs baseline: 2.1950x; 1.0084x over previous
#include <cuda_runtime.h>
#include <cuda_bf16.h>
#include <cstdint>

// ---------------- problem constants ----------------
#define BNB   16
#define SNS   64
#define CC    480
#define TT    8
#define FYH   28
#define FXW   28
#define OS8   8
#define NDF   256
#define KCENT 64
#define MROWS 1024              // BNB*SNS
#define KDIM  30720             // CC*OS8*OS8
#define HW    784               // FYH*FXW
#define NSPLIT 9                // split-K ways (6x107 + 3x106 slabs of k=32)

// ---------------- device scratch (static, no allocations) ----------------
__device__ float          g_featT[(size_t)BNB * HW * CC];     // [b][y][x][c] fp32
__device__ __nv_bfloat16  g_Ah[(size_t)MROWS * KDIM];         // A hi  [row][p*480+c]
__device__ __nv_bfloat16  g_Al[(size_t)MROWS * KDIM];         // A lo
__device__ __nv_bfloat16  g_Wh[(size_t)NDF * KDIM];           // Wt hi [n][p*480+c]
__device__ __nv_bfloat16  g_Wl[(size_t)NDF * KDIM];           // Wt lo
__device__ float          g_P[(size_t)NSPLIT * MROWS * NDF];  // split-K partials

// ---------------- helpers ----------------
#define SMEM_SWIZZLE_128B(byte_offset) \
    ((byte_offset) ^ (((byte_offset) >> 3) & 0x70))

__device__ __forceinline__ uint32_t smem_to_u32(const void* p) {
    uint32_t a;
    asm("{ .reg .u64 t; cvta.to.shared.u64 t, %1; cvt.u32.u64 %0, t; }" : "=r"(a) : "l"(p));
    return a;
}
__device__ __forceinline__ unsigned short bf16u(float x) {
    __nv_bfloat16 h = __float2bfloat16(x);
    return __bfloat16_as_ushort(h);
}
__device__ __forceinline__ float bf16f(unsigned short u) {
    return __bfloat162float(__ushort_as_bfloat16(u));
}

#define LDSM4(R0, R1, R2, R3, ADDR) \
    asm volatile("ldmatrix.sync.aligned.m8n8.x4.shared.b16 {%0,%1,%2,%3}, [%4];" \
        : "=r"(R0), "=r"(R1), "=r"(R2), "=r"(R3) : "r"(ADDR))

#define MMA16816(C, A, B0, B1) \
    asm volatile("mma.sync.aligned.m16n8k16.row.col.f32.bf16.bf16.f32 " \
        "{%0,%1,%2,%3}, {%4,%5,%6,%7}, {%8,%9}, {%0,%1,%2,%3};" \
        : "+f"((C)[0]), "+f"((C)[1]), "+f"((C)[2]), "+f"((C)[3]) \
        : "r"((A)[0]), "r"((A)[1]), "r"((A)[2]), "r"((A)[3]), "r"(B0), "r"(B1))

#define CPA16(DST, SRC) \
    asm volatile("cp.async.cg.shared.global [%0], [%1], 16;" :: "r"(DST), "l"(SRC))
#define CPA_COMMIT() asm volatile("cp.async.commit_group;" ::: "memory")
#define CPA_WAIT(N)  asm volatile("cp.async.wait_group %0;" :: "n"(N) : "memory")

// ---------------- K0: transpose feat [b][c][y][x] (T=last) -> [b][y][x][c] ----------------
__global__ void k_transpose(const float* __restrict__ zvis) {
    __shared__ float t[32][33];
    int b  = blockIdx.x;
    int c0 = blockIdx.y * 32;
    int h0 = blockIdx.z * 32;
    int tx = threadIdx.x, ty = threadIdx.y;
    const float* src = zvis + (size_t)b * CC * TT * HW + (size_t)(TT - 1) * HW;
#pragma unroll
    for (int j = 0; j < 32; j += 8) {
        int c = c0 + ty + j, h = h0 + tx;
        t[ty + j][tx] = (h < HW) ? src[(size_t)c * (TT * HW) + h] : 0.f;
    }
    __syncthreads();
    float* dst = g_featT + (size_t)b * HW * CC;
#pragma unroll
    for (int j = 0; j < 32; j += 8) {
        int h = h0 + ty + j, c = c0 + tx;
        if (h < HW) dst[(size_t)h * CC + c] = t[tx][ty + j];
    }
}

// ---------------- K0b: transpose+permute W[c*64+p][n] -> Wt hi/lo [n][p*480+c] ----------------
__global__ void k_wt(const float* __restrict__ W) {
    __shared__ float t[32][33];
    int kg0 = blockIdx.x * 32;     // 960 tiles over KDIM
    int n0  = blockIdx.y * 32;     // 8 tiles over NDF
    int tx = threadIdx.x, ty = threadIdx.y;   // 32 x 8
#pragma unroll
    for (int j = 0; j < 32; j += 8) {
        int kg = kg0 + ty + j;
        int c = kg % 480, p = kg / 480;
        t[ty + j][tx] = W[(size_t)(c * 64 + p) * NDF + n0 + tx];
    }
    __syncthreads();
#pragma unroll
    for (int j = 0; j < 32; j += 8) {
        int n = n0 + ty + j;
        float v = t[tx][ty + j];
        unsigned short h = bf16u(v);
        unsigned short l = bf16u(v - bf16f(h));
        g_Wh[(size_t)n * KDIM + kg0 + tx] = __ushort_as_bfloat16(h);
        g_Wl[(size_t)n * KDIM + kg0 + tx] = __ushort_as_bfloat16(l);
    }
}

// ---------------- K1: ROI-align pooling -> A hi/lo bf16 [row][p*480+c] ----------------
__global__ void k_roi(const float* __restrict__ bboxs) {
    int row = blockIdx.x;
    int b   = row >> 6;
    __shared__ int   s_off[64][4];
    __shared__ float s_w[64][4];
    __shared__ int   s_valid[64];
    int tid = threadIdx.x;
    if (tid < 64) {
        int p = tid;
        float bx1 = bboxs[row * 4 + 0], by1 = bboxs[row * 4 + 1];
        float bx2 = bboxs[row * 4 + 2], by2 = bboxs[row * 4 + 3];
        const float sX = 28.0f / 1920.0f, sY = 28.0f / 1080.0f;
        float x1 = bx1 * sX - 0.5f, y1 = by1 * sY - 0.5f;
        float x2 = bx2 * sX - 0.5f, y2 = by2 * sY - 0.5f;
        float bw = (x2 - x1) / 8.0f, bh = (y2 - y1) / 8.0f;
        int ix = p & 7, iy = p >> 3;
        float X = x1 + ((float)ix + 0.5f) * bw;
        float Y = y1 + ((float)iy + 0.5f) * bh;
        int valid = (Y > -1.0f) && (Y < 28.0f) && (X > -1.0f) && (X < 28.0f);
        float x = fminf(fmaxf(X, 0.f), 27.f);
        float y = fminf(fmaxf(Y, 0.f), 27.f);
        int x0 = (int)floorf(x), y0 = (int)floorf(y);
        int x1i = min(x0 + 1, 27), y1i = min(y0 + 1, 27);
        float lx = x - (float)x0, ly = y - (float)y0;
        s_off[p][0] = (y0 * 28 + x0) * (CC / 4);
        s_off[p][1] = (y0 * 28 + x1i) * (CC / 4);
        s_off[p][2] = (y1i * 28 + x0) * (CC / 4);
        s_off[p][3] = (y1i * 28 + x1i) * (CC / 4);
        s_w[p][0] = (1.f - ly) * (1.f - lx);
        s_w[p][1] = (1.f - ly) * lx;
        s_w[p][2] = ly * (1.f - lx);
        s_w[p][3] = ly * lx;
        s_valid[p] = valid;
    }
    __syncthreads();
    const float4* f = (const float4*)(g_featT + (size_t)b * HW * CC);
    uint2* outh = (uint2*)(g_Ah + (size_t)row * KDIM);
    uint2* outl = (uint2*)(g_Al + (size_t)row * KDIM);
    for (int i = tid; i < 64 * 120; i += 256) {
        int p = i / 120, c4 = i - p * 120;
        float4 r = make_float4(0.f, 0.f, 0.f, 0.f);
        if (s_valid[p]) {
            float4 v00 = f[s_off[p][0] + c4];
            float4 v01 = f[s_off[p][1] + c4];
            float4 v10 = f[s_off[p][2] + c4];
            float4 v11 = f[s_off[p][3] + c4];
            float w0 = s_w[p][0], w1 = s_w[p][1], w2 = s_w[p][2], w3 = s_w[p][3];
            r.x = v00.x * w0 + v01.x * w1 + v10.x * w2 + v11.x * w3;
            r.y = v00.y * w0 + v01.y * w1 + v10.y * w2 + v11.y * w3;
            r.z = v00.z * w0 + v01.z * w1 + v10.z * w2 + v11.z * w3;
            r.w = v00.w * w0 + v01.w * w1 + v10.w * w2 + v11.w * w3;
        }
        unsigned short h0 = bf16u(r.x), h1 = bf16u(r.y), h2 = bf16u(r.z), h3 = bf16u(r.w);
        unsigned short l0 = bf16u(r.x - bf16f(h0));
        unsigned short l1 = bf16u(r.y - bf16f(h1));
        unsigned short l2 = bf16u(r.z - bf16f(h2));
        unsigned short l3 = bf16u(r.w - bf16f(h3));
        outh[p * 120 + c4] = make_uint2((uint32_t)h0 | ((uint32_t)h1 << 16),
                                        (uint32_t)h2 | ((uint32_t)h3 << 16));
        outl[p * 120 + c4] = make_uint2((uint32_t)l0 | ((uint32_t)l1 << 16),
                                        (uint32_t)l2 | ((uint32_t)l3 << 16));
    }
}

// ---------------- K2: bf16x3 warp-MMA split-K GEMM (512 thr, 3-stage) ----------------
// CTA 128M x 128N, K slab = 32. Stage = 4 tiles (Ahi,Alo,Bhi,Blo) of
// 128x32 bf16 = 8KB each -> 32KB/stage, 3 stages = 96KB.
// 16 warps = 4M x 4N, warp tile 32x32. One __syncthreads per slab.
#define G3_STAGE 32768
#define G3_DYN   (3 * G3_STAGE + 1024)

__global__ void __launch_bounds__(512, 1) k_gemm3() {
    extern __shared__ char smem[];
    uint32_t sbase = (smem_to_u32(smem) + 1023u) & ~1023u;

    const int tid  = threadIdx.x;
    const int lane = tid & 31;
    const int wid  = tid >> 5;          // 0..15
    const int wm   = wid >> 2;          // M warp 0..3 (32 rows)
    const int wn   = wid & 3;           // N warp 0..3 (32 cols)

    const int n0    = blockIdx.x * 128; // 2 N tiles
    const int m0    = blockIdx.y * 128; // 8 M tiles
    const int split = blockIdx.z;       // 9 splits
    const int nsl   = (split < 6) ? 107 : 106;
    const int kbeg  = ((split < 6) ? split * 107 : 642 + (split - 6) * 106) * 32;

    // ---- cp.async mapping: 512 threads cover 128 rows x 4 x 16B chunks (one per tile)
    const int cr = tid >> 2;            // row 0..127
    const int cc = tid & 3;             // 16B chunk in 64B row
    const uint32_t dstc = SMEM_SWIZZLE_128B((uint32_t)(cr * 64 + cc * 16));
    const __nv_bfloat16* pAh = g_Ah + (size_t)(m0 + cr) * KDIM + cc * 8;
    const __nv_bfloat16* pAl = g_Al + (size_t)(m0 + cr) * KDIM + cc * 8;
    const __nv_bfloat16* pBh = g_Wh + (size_t)(n0 + cr) * KDIM + cc * 8;
    const __nv_bfloat16* pBl = g_Wl + (size_t)(n0 + cr) * KDIM + cc * 8;

    // ---- ldmatrix per-lane swizzled offsets (same mapping validated in R7)
    const int o = lane >> 3, li = lane & 7;
    uint32_t offA[2][2], offB[2][2];
#pragma unroll
    for (int mt = 0; mt < 2; mt++)
#pragma unroll
        for (int kb = 0; kb < 2; kb++) {
            int row  = wm * 32 + mt * 16 + (o & 1) * 8 + li;
            int colb = (o >> 1) * 16 + kb * 32;
            offA[mt][kb] = SMEM_SWIZZLE_128B((uint32_t)(row * 64 + colb));
        }
#pragma unroll
    for (int g4 = 0; g4 < 2; g4++)
#pragma unroll
        for (int kb = 0; kb < 2; kb++) {
            int row  = wn * 32 + g4 * 16 + (o >> 1) * 8 + li;
            int colb = (o & 1) * 16 + kb * 32;
            offB[g4][kb] = SMEM_SWIZZLE_128B((uint32_t)(row * 64 + colb));
        }

    float C[2][4][4];
#pragma unroll
    for (int mt = 0; mt < 2; mt++)
#pragma unroll
        for (int nt = 0; nt < 4; nt++)
#pragma unroll
            for (int q = 0; q < 4; q++) C[mt][nt][q] = 0.f;

    auto load_stage = [&](int s, int buf) {
        int kpos = kbeg + s * 32;
        uint32_t st = sbase + (uint32_t)buf * G3_STAGE;
        CPA16(st + dstc,           pAh + kpos);
        CPA16(st +  8192u + dstc,  pAl + kpos);
        CPA16(st + 16384u + dstc,  pBh + kpos);
        CPA16(st + 24576u + dstc,  pBl + kpos);
        CPA_COMMIT();
    };

    // prologue: stages 0,1
    load_stage(0, 0);
    load_stage(1, 1);

    for (int s = 0; s < nsl; s++) {
        int buf = s - (s / 3) * 3;       // s % 3
        if (s + 1 < nsl) { CPA_WAIT(1); } else { CPA_WAIT(0); }
        __syncthreads();
        // prefetch stage s+2 (overwrites buffer last read in slab s-1; sync above covers it)
        if (s + 2 < nsl) {
            int b2 = (s + 2) - ((s + 2) / 3) * 3;
            load_stage(s + 2, b2);
        }

        uint32_t base = sbase + (uint32_t)buf * G3_STAGE;
#pragma unroll
        for (int kb = 0; kb < 2; kb++) {
            uint32_t Ah[2][4], Al[2][4], Bh[4][2], Bl[4][2];
            LDSM4(Ah[0][0], Ah[0][1], Ah[0][2], Ah[0][3], base + offA[0][kb]);
            LDSM4(Ah[1][0], Ah[1][1], Ah[1][2], Ah[1][3], base + offA[1][kb]);
            LDSM4(Al[0][0], Al[0][1], Al[0][2], Al[0][3], base + 8192u + offA[0][kb]);
            LDSM4(Al[1][0], Al[1][1], Al[1][2], Al[1][3], base + 8192u + offA[1][kb]);
#pragma unroll
            for (int g4 = 0; g4 < 2; g4++)
                LDSM4(Bh[2 * g4][0], Bh[2 * g4][1], Bh[2 * g4 + 1][0], Bh[2 * g4 + 1][1],
                      base + 16384u + offB[g4][kb]);
#pragma unroll
            for (int g4 = 0; g4 < 2; g4++)
                LDSM4(Bl[2 * g4][0], Bl[2 * g4][1], Bl[2 * g4 + 1][0], Bl[2 * g4 + 1][1],
                      base + 24576u + offB[g4][kb]);
#pragma unroll
            for (int mt = 0; mt < 2; mt++)
#pragma unroll
                for (int nt = 0; nt < 4; nt++) {
                    MMA16816(C[mt][nt], Ah[mt], Bh[nt][0], Bh[nt][1]);
                    MMA16816(C[mt][nt], Ah[mt], Bl[nt][0], Bl[nt][1]);
                    MMA16816(C[mt][nt], Al[mt], Bh[nt][0], Bh[nt][1]);
                }
        }
    }

    // ---- epilogue: C frags -> g_P
    float* dst = g_P + (size_t)split * MROWS * NDF;
    const int gq = lane >> 2, tq = lane & 3;
#pragma unroll
    for (int mt = 0; mt < 2; mt++)
#pragma unroll
        for (int nt = 0; nt < 4; nt++) {
            int rr = m0 + wm * 32 + mt * 16 + gq;
            int nn = n0 + wn * 32 + nt * 8 + tq * 2;
            *(float2*)(dst + (size_t)rr * NDF + nn)       = make_float2(C[mt][nt][0], C[mt][nt][1]);
            *(float2*)(dst + (size_t)(rr + 8) * NDF + nn) = make_float2(C[mt][nt][2], C[mt][nt][3]);
        }
}

// ---------------- K3: reduce split-K + bias + spatial, distances, s, argmax ----------------
__global__ void k_final(const float* __restrict__ bboxs,
                        const float* __restrict__ b_vis,
                        const float* __restrict__ W_spc,
                        const float* __restrict__ b_spc,
                        const float* __restrict__ centroids,
                        float* __restrict__ out) {
    int row  = blockIdx.x;
    int tid  = threadIdx.x;
    int lane = tid & 31;
    int w    = tid >> 5;
    __shared__ float zs[NDF];
    __shared__ float sv[KCENT];
    __shared__ float s_sum;
    __shared__ int   s_arg;

    float bx1 = bboxs[row * 4 + 0], by1 = bboxs[row * 4 + 1];
    float bx2 = bboxs[row * 4 + 2], by2 = bboxs[row * 4 + 3];
    float cx = bx1 + (bx2 - bx1) * 0.5f;
    float cy = by1 + (by2 - by1) * 0.5f;
    float dx = cx - 960.0f, dy = cy - 540.0f;
    float nrm = sqrtf(dx * dx + dy * dy) / sqrtf(960.0f * 960.0f + 540.0f * 540.0f);

    const float* P = g_P + (size_t)row * NDF + tid;
    float acc = 0.f;
#pragma unroll
    for (int s = 0; s < NSPLIT; s++)
        acc += P[(size_t)s * MROWS * NDF];
    float z = acc + b_vis[tid] + nrm * W_spc[tid] + b_spc[tid];
    out[(size_t)row * NDF + tid] = z;
    zs[tid] = z;
    __syncthreads();

#pragma unroll
    for (int kk = 0; kk < 8; kk++) {
        int k = w * 8 + kk;
        const float* cen = centroids + (size_t)k * NDF;
        float d2 = 0.f;
#pragma unroll
        for (int j = 0; j < 8; j++) {
            int n = j * 32 + lane;
            float t = zs[n] - cen[n];
            d2 = fmaf(t, t, d2);
        }
#pragma unroll
        for (int oo = 16; oo > 0; oo >>= 1) d2 += __shfl_xor_sync(0xffffffffu, d2, oo);
        if (lane == 0) sv[k] = 1.0f / (1.0f + sqrtf(d2));
    }
    __syncthreads();

    if (tid < 32) {
        float a = sv[tid], b = sv[tid + 32];
        float vsum = a + b;
        float m  = (a >= b) ? a : b;
        int   mi = (a >= b) ? tid : tid + 32;
#pragma unroll
        for (int oo = 16; oo > 0; oo >>= 1) {
            vsum += __shfl_xor_sync(0xffffffffu, vsum, oo);
            float om = __shfl_xor_sync(0xffffffffu, m, oo);
            int   oi = __shfl_xor_sync(0xffffffffu, mi, oo);
            if (om > m || (om == m && oi < mi)) { m = om; mi = oi; }
        }
        if (tid == 0) { s_sum = vsum; s_arg = mi; }
    }
    __syncthreads();

    if (tid < KCENT)
        out[(size_t)MROWS * NDF + (size_t)row * KCENT + tid] = sv[tid] / s_sum;
    if (tid == 0)
        out[(size_t)MROWS * NDF + (size_t)MROWS * KCENT + row] = (float)s_arg;
}

// ---------------- launch ----------------
extern "C" void kernel_launch(void* const* d_in, const int* in_sizes, int n_in,
                              void* d_out, int out_size) {
    const float* z_vis = (const float*)d_in[0];
    const float* bboxs = (const float*)d_in[1];
    const float* W_vis = (const float*)d_in[2];
    const float* b_vis = (const float*)d_in[3];
    const float* W_spc = (const float*)d_in[4];
    const float* b_spc = (const float*)d_in[5];
    const float* cent  = (const float*)d_in[6];
    float* out = (float*)d_out;
    (void)in_sizes; (void)n_in; (void)out_size;

    cudaFuncSetAttribute(k_gemm3, cudaFuncAttributeMaxDynamicSharedMemorySize, G3_DYN);

    k_transpose<<<dim3(16, 15, 25), dim3(32, 8)>>>(z_vis);
    k_wt<<<dim3(KDIM / 32, NDF / 32), dim3(32, 8)>>>(W_vis);
    k_roi<<<MROWS, 256>>>(bboxs);
    k_gemm3<<<dim3(2, 8, NSPLIT), 512, G3_DYN>>>();
    k_final<<<MROWS, 256>>>(bboxs, b_vis, W_spc, b_spc, cent, out);
}

// round 9
// speedup vs baseline: 2.4321x; 1.1080x over previous
#include <cuda_runtime.h>
#include <cuda_bf16.h>
#include <cstdint>

// ---------------- problem constants ----------------
#define BNB   16
#define SNS   64
#define CC    480
#define TT    8
#define FYH   28
#define FXW   28
#define OS8   8
#define NDF   256
#define KCENT 64
#define MROWS 1024              // BNB*SNS
#define KDIM  30720             // CC*OS8*OS8
#define HW    784               // FYH*FXW
#define NSPLIT 9                // split-K ways (6x53 + 3x54 slabs of k=64)

// ---------------- device scratch (static, no allocations) ----------------
__device__ float          g_featT[(size_t)BNB * HW * CC];     // [b][y][x][c] fp32
__device__ __nv_bfloat16  g_Ah[(size_t)MROWS * KDIM];         // A hi  [row][p*480+c]
__device__ __nv_bfloat16  g_Al[(size_t)MROWS * KDIM];         // A lo
__device__ __nv_bfloat16  g_Wh[(size_t)NDF * KDIM];           // Wt hi [n][p*480+c]
__device__ __nv_bfloat16  g_Wl[(size_t)NDF * KDIM];           // Wt lo
__device__ float          g_P[(size_t)NSPLIT * MROWS * NDF];  // split-K partials

// ---------------- helpers ----------------
#define SMEM_SWIZZLE_128B(byte_offset) \
    ((byte_offset) ^ (((byte_offset) >> 3) & 0x70))

__device__ __forceinline__ uint32_t smem_to_u32(const void* p) {
    uint32_t a;
    asm("{ .reg .u64 t; cvta.to.shared.u64 t, %1; cvt.u32.u64 %0, t; }" : "=r"(a) : "l"(p));
    return a;
}
__device__ __forceinline__ unsigned short bf16u(float x) {
    __nv_bfloat16 h = __float2bfloat16(x);
    return __bfloat16_as_ushort(h);
}
__device__ __forceinline__ float bf16f(unsigned short u) {
    return __bfloat162float(__ushort_as_bfloat16(u));
}

#define LDSM4(R0, R1, R2, R3, ADDR) \
    asm volatile("ldmatrix.sync.aligned.m8n8.x4.shared.b16 {%0,%1,%2,%3}, [%4];" \
        : "=r"(R0), "=r"(R1), "=r"(R2), "=r"(R3) : "r"(ADDR))

#define MMA16816(C, A, B0, B1) \
    asm volatile("mma.sync.aligned.m16n8k16.row.col.f32.bf16.bf16.f32 " \
        "{%0,%1,%2,%3}, {%4,%5,%6,%7}, {%8,%9}, {%0,%1,%2,%3};" \
        : "+f"((C)[0]), "+f"((C)[1]), "+f"((C)[2]), "+f"((C)[3]) \
        : "r"((A)[0]), "r"((A)[1]), "r"((A)[2]), "r"((A)[3]), "r"(B0), "r"(B1))

#define CPA16(DST, SRC) \
    asm volatile("cp.async.cg.shared.global [%0], [%1], 16;" :: "r"(DST), "l"(SRC))
#define CPA_COMMIT() asm volatile("cp.async.commit_group;" ::: "memory")
#define CPA_WAIT(N)  asm volatile("cp.async.wait_group %0;" :: "n"(N) : "memory")

// ---------------- K0: transpose feat [b][c][y][x] (T=last) -> [b][y][x][c] ----------------
__global__ void k_transpose(const float* __restrict__ zvis) {
    __shared__ float t[32][33];
    int b  = blockIdx.x;
    int c0 = blockIdx.y * 32;
    int h0 = blockIdx.z * 32;
    int tx = threadIdx.x, ty = threadIdx.y;
    const float* src = zvis + (size_t)b * CC * TT * HW + (size_t)(TT - 1) * HW;
#pragma unroll
    for (int j = 0; j < 32; j += 8) {
        int c = c0 + ty + j, h = h0 + tx;
        t[ty + j][tx] = (h < HW) ? src[(size_t)c * (TT * HW) + h] : 0.f;
    }
    __syncthreads();
    float* dst = g_featT + (size_t)b * HW * CC;
#pragma unroll
    for (int j = 0; j < 32; j += 8) {
        int h = h0 + ty + j, c = c0 + tx;
        if (h < HW) dst[(size_t)h * CC + c] = t[tx][ty + j];
    }
}

// ---------------- K0b: transpose+permute W[c*64+p][n] -> Wt hi/lo [n][p*480+c] ----------------
__global__ void k_wt(const float* __restrict__ W) {
    __shared__ float t[32][33];
    int kg0 = blockIdx.x * 32;     // 960 tiles over KDIM
    int n0  = blockIdx.y * 32;     // 8 tiles over NDF
    int tx = threadIdx.x, ty = threadIdx.y;   // 32 x 8
#pragma unroll
    for (int j = 0; j < 32; j += 8) {
        int kg = kg0 + ty + j;
        int c = kg % 480, p = kg / 480;
        t[ty + j][tx] = W[(size_t)(c * 64 + p) * NDF + n0 + tx];
    }
    __syncthreads();
#pragma unroll
    for (int j = 0; j < 32; j += 8) {
        int n = n0 + ty + j;
        float v = t[tx][ty + j];
        unsigned short h = bf16u(v);
        unsigned short l = bf16u(v - bf16f(h));
        g_Wh[(size_t)n * KDIM + kg0 + tx] = __ushort_as_bfloat16(h);
        g_Wl[(size_t)n * KDIM + kg0 + tx] = __ushort_as_bfloat16(l);
    }
}

// ---------------- K1: ROI-align pooling -> A hi/lo bf16 [row][p*480+c] ----------------
__global__ void k_roi(const float* __restrict__ bboxs) {
    int row = blockIdx.x;
    int b   = row >> 6;
    __shared__ int   s_off[64][4];
    __shared__ float s_w[64][4];
    __shared__ int   s_valid[64];
    int tid = threadIdx.x;
    if (tid < 64) {
        int p = tid;
        float bx1 = bboxs[row * 4 + 0], by1 = bboxs[row * 4 + 1];
        float bx2 = bboxs[row * 4 + 2], by2 = bboxs[row * 4 + 3];
        const float sX = 28.0f / 1920.0f, sY = 28.0f / 1080.0f;
        float x1 = bx1 * sX - 0.5f, y1 = by1 * sY - 0.5f;
        float x2 = bx2 * sX - 0.5f, y2 = by2 * sY - 0.5f;
        float bw = (x2 - x1) / 8.0f, bh = (y2 - y1) / 8.0f;
        int ix = p & 7, iy = p >> 3;
        float X = x1 + ((float)ix + 0.5f) * bw;
        float Y = y1 + ((float)iy + 0.5f) * bh;
        int valid = (Y > -1.0f) && (Y < 28.0f) && (X > -1.0f) && (X < 28.0f);
        float x = fminf(fmaxf(X, 0.f), 27.f);
        float y = fminf(fmaxf(Y, 0.f), 27.f);
        int x0 = (int)floorf(x), y0 = (int)floorf(y);
        int x1i = min(x0 + 1, 27), y1i = min(y0 + 1, 27);
        float lx = x - (float)x0, ly = y - (float)y0;
        s_off[p][0] = (y0 * 28 + x0) * (CC / 4);
        s_off[p][1] = (y0 * 28 + x1i) * (CC / 4);
        s_off[p][2] = (y1i * 28 + x0) * (CC / 4);
        s_off[p][3] = (y1i * 28 + x1i) * (CC / 4);
        s_w[p][0] = (1.f - ly) * (1.f - lx);
        s_w[p][1] = (1.f - ly) * lx;
        s_w[p][2] = ly * (1.f - lx);
        s_w[p][3] = ly * lx;
        s_valid[p] = valid;
    }
    __syncthreads();
    const float4* f = (const float4*)(g_featT + (size_t)b * HW * CC);
    uint2* outh = (uint2*)(g_Ah + (size_t)row * KDIM);
    uint2* outl = (uint2*)(g_Al + (size_t)row * KDIM);
    for (int i = tid; i < 64 * 120; i += 256) {
        int p = i / 120, c4 = i - p * 120;
        float4 r = make_float4(0.f, 0.f, 0.f, 0.f);
        if (s_valid[p]) {
            float4 v00 = f[s_off[p][0] + c4];
            float4 v01 = f[s_off[p][1] + c4];
            float4 v10 = f[s_off[p][2] + c4];
            float4 v11 = f[s_off[p][3] + c4];
            float w0 = s_w[p][0], w1 = s_w[p][1], w2 = s_w[p][2], w3 = s_w[p][3];
            r.x = v00.x * w0 + v01.x * w1 + v10.x * w2 + v11.x * w3;
            r.y = v00.y * w0 + v01.y * w1 + v10.y * w2 + v11.y * w3;
            r.z = v00.z * w0 + v01.z * w1 + v10.z * w2 + v11.z * w3;
            r.w = v00.w * w0 + v01.w * w1 + v10.w * w2 + v11.w * w3;
        }
        unsigned short h0 = bf16u(r.x), h1 = bf16u(r.y), h2 = bf16u(r.z), h3 = bf16u(r.w);
        unsigned short l0 = bf16u(r.x - bf16f(h0));
        unsigned short l1 = bf16u(r.y - bf16f(h1));
        unsigned short l2 = bf16u(r.z - bf16f(h2));
        unsigned short l3 = bf16u(r.w - bf16f(h3));
        outh[p * 120 + c4] = make_uint2((uint32_t)h0 | ((uint32_t)h1 << 16),
                                        (uint32_t)h2 | ((uint32_t)h3 << 16));
        outl[p * 120 + c4] = make_uint2((uint32_t)l0 | ((uint32_t)l1 << 16),
                                        (uint32_t)l2 | ((uint32_t)l3 << 16));
    }
}

// ---------------- K2: bf16x3 warp-MMA split-K GEMM (512 thr, slab=64, frag pipeline) ----------------
// CTA 128M x 128N, K slab = 64 (4 kb of 16). Stage = 4 tiles (Ahi,Alo,Bhi,Blo)
// of 128 rows x 128B = 16KB each -> 64KB/stage, 3 stages = 192KB.
// 16 warps = 4M x 4N, warp tile 32x32. Register fragment double-buffering:
// frags(kb+1) load during MMA(kb). One __syncthreads per slab.
#define G3_STAGE 65536
#define G3_TA_LO 16384u
#define G3_TB_HI 32768u
#define G3_TB_LO 49152u
#define G3_DYN   (3 * G3_STAGE + 1024)
#define KBS 4                    // kb per slab

struct Frag {
    uint32_t Ah[2][4], Al[2][4], Bh[4][2], Bl[4][2];
};

__device__ __forceinline__ void ldsm_kb(Frag& F, uint32_t st, int kb,
                                        const uint32_t* baseA, const uint32_t* baseB) {
    const uint32_t ko = (uint32_t)kb * 32u;
#pragma unroll
    for (int mt = 0; mt < 2; mt++) {
        uint32_t sw = SMEM_SWIZZLE_128B(baseA[mt] + ko);
        LDSM4(F.Ah[mt][0], F.Ah[mt][1], F.Ah[mt][2], F.Ah[mt][3], st + sw);
        LDSM4(F.Al[mt][0], F.Al[mt][1], F.Al[mt][2], F.Al[mt][3], st + G3_TA_LO + sw);
    }
#pragma unroll
    for (int g = 0; g < 2; g++) {
        uint32_t sw = SMEM_SWIZZLE_128B(baseB[g] + ko);
        LDSM4(F.Bh[2 * g][0], F.Bh[2 * g][1], F.Bh[2 * g + 1][0], F.Bh[2 * g + 1][1],
              st + G3_TB_HI + sw);
        LDSM4(F.Bl[2 * g][0], F.Bl[2 * g][1], F.Bl[2 * g + 1][0], F.Bl[2 * g + 1][1],
              st + G3_TB_LO + sw);
    }
}

__device__ __forceinline__ void mma_frag(float C[2][4][4], const Frag& F) {
    // pass-major: 8 independent MMAs per pass, accumulator chains spaced apart
#pragma unroll
    for (int mt = 0; mt < 2; mt++)
#pragma unroll
        for (int nt = 0; nt < 4; nt++)
            MMA16816(C[mt][nt], F.Ah[mt], F.Bh[nt][0], F.Bh[nt][1]);
#pragma unroll
    for (int mt = 0; mt < 2; mt++)
#pragma unroll
        for (int nt = 0; nt < 4; nt++)
            MMA16816(C[mt][nt], F.Ah[mt], F.Bl[nt][0], F.Bl[nt][1]);
#pragma unroll
    for (int mt = 0; mt < 2; mt++)
#pragma unroll
        for (int nt = 0; nt < 4; nt++)
            MMA16816(C[mt][nt], F.Al[mt], F.Bh[nt][0], F.Bh[nt][1]);
}

__global__ void __launch_bounds__(512) k_gemm3() {
    extern __shared__ char smem[];
    uint32_t sbase = (smem_to_u32(smem) + 1023u) & ~1023u;

    const int tid  = threadIdx.x;
    const int lane = tid & 31;
    const int wid  = tid >> 5;          // 0..15
    const int wm   = wid >> 2;          // M warp 0..3 (32 rows)
    const int wn   = wid & 3;           // N warp 0..3 (32 cols)

    const int n0    = blockIdx.x * 128; // 2 N tiles
    const int m0    = blockIdx.y * 128; // 8 M tiles
    const int split = blockIdx.z;       // 9 splits
    const int nsl   = (split < 6) ? 53 : 54;                       // 6*53+3*54 = 480 slabs
    const int kbeg  = ((split < 6) ? split * 53 : 318 + (split - 6) * 54) * 64;

    // ---- cp.async mapping: 1024 16B-chunks per tile, 2 per thread
    const int r0 = tid >> 3;            // rows 0..63
    const int c0 = tid & 7;             // 16B chunk in 128B row
    const int r1 = r0 + 64;             // rows 64..127
    const uint32_t dst0 = SMEM_SWIZZLE_128B((uint32_t)(r0 * 128 + c0 * 16));
    const uint32_t dst1 = SMEM_SWIZZLE_128B((uint32_t)(r1 * 128 + c0 * 16));
    const __nv_bfloat16* pAh = g_Ah + (size_t)(m0 + r0) * KDIM + c0 * 8;
    const __nv_bfloat16* pAl = g_Al + (size_t)(m0 + r0) * KDIM + c0 * 8;
    const __nv_bfloat16* pBh = g_Wh + (size_t)(n0 + r0) * KDIM + c0 * 8;
    const __nv_bfloat16* pBl = g_Wl + (size_t)(n0 + r0) * KDIM + c0 * 8;
    const size_t rstep = (size_t)64 * KDIM;

    // ---- ldmatrix per-lane UNswizzled base offsets (swizzle applied per kb)
    const int o = lane >> 3, li = lane & 7;
    uint32_t baseA[2], baseB[2];
#pragma unroll
    for (int mt = 0; mt < 2; mt++)
        baseA[mt] = (uint32_t)((wm * 32 + mt * 16 + (o & 1) * 8 + li) * 128 + (o >> 1) * 16);
#pragma unroll
    for (int g = 0; g < 2; g++)
        baseB[g]  = (uint32_t)((wn * 32 + g * 16 + (o >> 1) * 8 + li) * 128 + (o & 1) * 16);

    float C[2][4][4];
#pragma unroll
    for (int mt = 0; mt < 2; mt++)
#pragma unroll
        for (int nt = 0; nt < 4; nt++)
#pragma unroll
            for (int q = 0; q < 4; q++) C[mt][nt][q] = 0.f;

    auto load_stage = [&](int s, int buf) {
        int kpos = kbeg + s * 64;
        uint32_t st = sbase + (uint32_t)buf * G3_STAGE;
        CPA16(st + dst0,            pAh + kpos);
        CPA16(st + dst1,            pAh + rstep + kpos);
        CPA16(st + G3_TA_LO + dst0, pAl + kpos);
        CPA16(st + G3_TA_LO + dst1, pAl + rstep + kpos);
        CPA16(st + G3_TB_HI + dst0, pBh + kpos);
        CPA16(st + G3_TB_HI + dst1, pBh + rstep + kpos);
        CPA16(st + G3_TB_LO + dst0, pBl + kpos);
        CPA16(st + G3_TB_LO + dst1, pBl + rstep + kpos);
        CPA_COMMIT();
    };

    // prologue: stages 0,1
    load_stage(0, 0);
    load_stage(1, 1);

    Frag F0, F1;
    for (int s = 0; s < nsl; s++) {
        int buf = s - (s / 3) * 3;       // s % 3
        if (s + 1 < nsl) { CPA_WAIT(1); } else { CPA_WAIT(0); }
        __syncthreads();
        // prefetch stage s+2 (its buffer was last read in slab s-1; sync covers reuse)
        if (s + 2 < nsl) {
            int b2 = (s + 2) - ((s + 2) / 3) * 3;
            load_stage(s + 2, b2);
        }

        uint32_t st = sbase + (uint32_t)buf * G3_STAGE;
        // software-pipelined fragments: load(kb+1) overlaps mma(kb)
        ldsm_kb(F0, st, 0, baseA, baseB);
        ldsm_kb(F1, st, 1, baseA, baseB);
        mma_frag(C, F0);
        ldsm_kb(F0, st, 2, baseA, baseB);
        mma_frag(C, F1);
        ldsm_kb(F1, st, 3, baseA, baseB);
        mma_frag(C, F0);
        mma_frag(C, F1);
    }

    // ---- epilogue: C frags -> g_P
    float* dst = g_P + (size_t)split * MROWS * NDF;
    const int gq = lane >> 2, tq = lane & 3;
#pragma unroll
    for (int mt = 0; mt < 2; mt++)
#pragma unroll
        for (int nt = 0; nt < 4; nt++) {
            int rr = m0 + wm * 32 + mt * 16 + gq;
            int nn = n0 + wn * 32 + nt * 8 + tq * 2;
            *(float2*)(dst + (size_t)rr * NDF + nn)       = make_float2(C[mt][nt][0], C[mt][nt][1]);
            *(float2*)(dst + (size_t)(rr + 8) * NDF + nn) = make_float2(C[mt][nt][2], C[mt][nt][3]);
        }
}

// ---------------- K3: reduce split-K + bias + spatial, distances, s, argmax ----------------
__global__ void k_final(const float* __restrict__ bboxs,
                        const float* __restrict__ b_vis,
                        const float* __restrict__ W_spc,
                        const float* __restrict__ b_spc,
                        const float* __restrict__ centroids,
                        float* __restrict__ out) {
    int row  = blockIdx.x;
    int tid  = threadIdx.x;
    int lane = tid & 31;
    int w    = tid >> 5;
    __shared__ float zs[NDF];
    __shared__ float sv[KCENT];
    __shared__ float s_sum;
    __shared__ int   s_arg;

    float bx1 = bboxs[row * 4 + 0], by1 = bboxs[row * 4 + 1];
    float bx2 = bboxs[row * 4 + 2], by2 = bboxs[row * 4 + 3];
    float cx = bx1 + (bx2 - bx1) * 0.5f;
    float cy = by1 + (by2 - by1) * 0.5f;
    float dx = cx - 960.0f, dy = cy - 540.0f;
    float nrm = sqrtf(dx * dx + dy * dy) / sqrtf(960.0f * 960.0f + 540.0f * 540.0f);

    const float* P = g_P + (size_t)row * NDF + tid;
    float acc = 0.f;
#pragma unroll
    for (int s = 0; s < NSPLIT; s++)
        acc += P[(size_t)s * MROWS * NDF];
    float z = acc + b_vis[tid] + nrm * W_spc[tid] + b_spc[tid];
    out[(size_t)row * NDF + tid] = z;
    zs[tid] = z;
    __syncthreads();

#pragma unroll
    for (int kk = 0; kk < 8; kk++) {
        int k = w * 8 + kk;
        const float* cen = centroids + (size_t)k * NDF;
        float d2 = 0.f;
#pragma unroll
        for (int j = 0; j < 8; j++) {
            int n = j * 32 + lane;
            float t = zs[n] - cen[n];
            d2 = fmaf(t, t, d2);
        }
#pragma unroll
        for (int oo = 16; oo > 0; oo >>= 1) d2 += __shfl_xor_sync(0xffffffffu, d2, oo);
        if (lane == 0) sv[k] = 1.0f / (1.0f + sqrtf(d2));
    }
    __syncthreads();

    if (tid < 32) {
        float a = sv[tid], b = sv[tid + 32];
        float vsum = a + b;
        float m  = (a >= b) ? a : b;
        int   mi = (a >= b) ? tid : tid + 32;
#pragma unroll
        for (int oo = 16; oo > 0; oo >>= 1) {
            vsum += __shfl_xor_sync(0xffffffffu, vsum, oo);
            float om = __shfl_xor_sync(0xffffffffu, m, oo);
            int   oi = __shfl_xor_sync(0xffffffffu, mi, oo);
            if (om > m || (om == m && oi < mi)) { m = om; mi = oi; }
        }
        if (tid == 0) { s_sum = vsum; s_arg = mi; }
    }
    __syncthreads();

    if (tid < KCENT)
        out[(size_t)MROWS * NDF + (size_t)row * KCENT + tid] = sv[tid] / s_sum;
    if (tid == 0)
        out[(size_t)MROWS * NDF + (size_t)MROWS * KCENT + row] = (float)s_arg;
}

// ---------------- launch ----------------
extern "C" void kernel_launch(void* const* d_in, const int* in_sizes, int n_in,
                              void* d_out, int out_size) {
    const float* z_vis = (const float*)d_in[0];
    const float* bboxs = (const float*)d_in[1];
    const float* W_vis = (const float*)d_in[2];
    const float* b_vis = (const float*)d_in[3];
    const float* W_spc = (const float*)d_in[4];
    const float* b_spc = (const float*)d_in[5];
    const float* cent  = (const float*)d_in[6];
    float* out = (float*)d_out;
    (void)in_sizes; (void)n_in; (void)out_size;

    cudaFuncSetAttribute(k_gemm3, cudaFuncAttributeMaxDynamicSharedMemorySize, G3_DYN);

    k_transpose<<<dim3(16, 15, 25), dim3(32, 8)>>>(z_vis);
    k_wt<<<dim3(KDIM / 32, NDF / 32), dim3(32, 8)>>>(W_vis);
    k_roi<<<MROWS, 256>>>(bboxs);
    k_gemm3<<<dim3(2, 8, NSPLIT), 512, G3_DYN>>>();
    k_final<<<MROWS, 256>>>(bboxs, b_vis, W_spc, b_spc, cent, out);
}